// round 9
// baseline (speedup 1.0000x reference)
#include <cuda_runtime.h>
#include <cuda_bf16.h>
#include <stdint.h>

typedef unsigned long long ull;

#define NB   1024
#define SS   16
#define AA   8
#define NACT 16
#define SD   256
#define EM   256
#define NROWS (NB*SS*AA)   // 131072

// ---------------- device scratch ----------------
__device__ float g_sW1[NB*EM];
__device__ float g_v[NB];
__device__ unsigned char g_pos[NROWS];
// h1 A-fragments: [b][mblk(8)][kblk(16)][lane(32)][reg(4)] u32, hi and lo
__device__ uint32_t g_Ah[(size_t)NB*8*16*32*4];
__device__ uint32_t g_Al[(size_t)NB*8*16*32*4];
// W2 B-fragments: [kblk(16)][nblk(32)][lane(32)][reg(2)] u32 (R5 layout)
__device__ uint32_t g_Bh[16*32*32*2];
__device__ uint32_t g_Bl[16*32*32*2];

// ---------------- threefry2x32 (JAX exact, key(42)) ----------------
__device__ __forceinline__ uint32_t rotl(uint32_t x, int r){ return (x<<r)|(x>>(32-r)); }
__device__ __forceinline__ void threefry2x32(uint32_t c0, uint32_t c1, uint32_t &o0, uint32_t &o1){
  const uint32_t k0 = 0u, k1v = 42u, k2 = 0u ^ 42u ^ 0x1BD11BDAu;
  uint32_t x0 = c0 + k0;
  uint32_t x1 = c1 + k1v;
#define TF_R(rot) { x0 += x1; x1 = rotl(x1, rot); x1 ^= x0; }
  TF_R(13) TF_R(15) TF_R(26) TF_R(6)
  x0 += k1v; x1 += k2 + 1u;
  TF_R(17) TF_R(29) TF_R(16) TF_R(24)
  x0 += k2;  x1 += k0 + 2u;
  TF_R(13) TF_R(15) TF_R(26) TF_R(6)
  x0 += k0;  x1 += k1v + 3u;
  TF_R(17) TF_R(29) TF_R(16) TF_R(24)
  x0 += k1v; x1 += k2 + 4u;
  TF_R(13) TF_R(15) TF_R(26) TF_R(6)
  x0 += k2;  x1 += k0 + 5u;
#undef TF_R
  o0 = x0; o1 = x1;
}
__device__ __forceinline__ float bits_to_unit(uint32_t bits){
  return __uint_as_float(0x3f800000u | (bits >> 9)) - 1.0f;
}

// ---------------- packed helpers ----------------
__device__ __forceinline__ ull pack2(float x){
  ull r; unsigned u = __float_as_uint(x);
  asm("mov.b64 %0, {%1,%1};" : "=l"(r) : "r"(u));
  return r;
}
__device__ __forceinline__ void fma2(ull& d, ull a, ull b){
  asm("fma.rn.f32x2 %0, %1, %2, %0;" : "+l"(d) : "l"(a), "l"(b));
}
__device__ __forceinline__ float2 unpack2(ull v){
  unsigned lo, hi; asm("mov.b64 {%0,%1}, %2;" : "=r"(lo), "=r"(hi) : "l"(v));
  return make_float2(__uint_as_float(lo), __uint_as_float(hi));
}
// pack two f32 to bf16x2: low half = v0, high half = v1
__device__ __forceinline__ uint32_t pack_bf16x2(float v0, float v1){
  uint32_t r;
  asm("cvt.rn.bf16x2.f32 %0, %1, %2;" : "=r"(r) : "f"(v1), "f"(v0));
  return r;
}
// hi/lo split of a value pair: h = bf16x2(v0,v1), l = bf16x2(v0-hi0, v1-hi1)
__device__ __forceinline__ void split2(float v0, float v1, uint32_t &h, uint32_t &l){
  h = pack_bf16x2(v0, v1);
  float h0 = __uint_as_float(h << 16);
  float h1 = __uint_as_float(h & 0xFFFF0000u);
  l = pack_bf16x2(v0 - h0, v1 - h1);
}
__device__ __forceinline__ void split_bf16(float v, uint32_t &h, uint32_t &l){
  __nv_bfloat16 hb = __float2bfloat16(v);
  float lf = v - __bfloat162float(hb);
  __nv_bfloat16 lb = __float2bfloat16(lf);
  h = (uint32_t)__bfloat16_as_ushort(hb);
  l = (uint32_t)__bfloat16_as_ushort(lb);
}

__device__ __forceinline__ void mma16816(float* d, const uint32_t* a, uint32_t b0, uint32_t b1){
  asm volatile("mma.sync.aligned.m16n8k16.row.col.f32.bf16.bf16.f32 "
    "{%0,%1,%2,%3}, {%4,%5,%6,%7}, {%8,%9}, {%0,%1,%2,%3};"
    : "+f"(d[0]),"+f"(d[1]),"+f"(d[2]),"+f"(d[3])
    : "r"(a[0]),"r"(a[1]),"r"(a[2]),"r"(a[3]), "r"(b0),"r"(b1));
}

// ============ K0: W2 -> B fragments ============
__global__ void k0_prepW2(const float* __restrict__ W2){
  int idx = blockIdx.x*256 + threadIdx.x;   // 32768
  int kp = idx >> 8, n = idx & 255;
  int k = kp*2;
  float v0 = W2[k*EM + n];
  float v1 = W2[(k+1)*EM + n];
  uint32_t h0,l0,h1,l1;
  split_bf16(v0,h0,l0); split_bf16(v1,h1,l1);
  uint32_t hi = h0 | (h1<<16);
  uint32_t lo = l0 | (l1<<16);
  int kblk = kp>>3;
  int reg  = (kp>>2)&1;
  int lane = (n&7)*4 + (kp&3);
  int nblk = n>>3;
  int bidx = ((kblk*32+nblk)*32+lane)*2 + reg;
  g_Bh[bidx] = hi;
  g_Bl[bidx] = lo;
}

// ============ K1: per-b state terms, 4 b per CTA ============
__global__ void __launch_bounds__(256) k1_state(const float* __restrict__ st,
                         const float* __restrict__ W1,
                         const float* __restrict__ b1, const float* __restrict__ Vw1,
                         const float* __restrict__ Vb1, const float* __restrict__ Vw2,
                         const float* __restrict__ Vb2){
  const int b0 = blockIdx.x * 4;
  const int n  = threadIdx.x;
  __shared__ float s_st[4][SD];
  __shared__ float red[4][EM];
  #pragma unroll
  for(int bi=0;bi<4;bi++) s_st[bi][n] = st[(b0+bi)*SD + n];
  __syncthreads();
  float acc[4], accv[4];
  float bb1 = b1[n], vbb = Vb1[n];
  #pragma unroll
  for(int bi=0;bi<4;bi++){ acc[bi]=bb1; accv[bi]=vbb; }
  #pragma unroll 4
  for(int k=0;k<SD;k++){
    float w  = W1 [k*EM + n];
    float vw = Vw1[k*EM + n];
    #pragma unroll
    for(int bi=0;bi<4;bi++){
      float sv = s_st[bi][k];
      acc[bi]  = fmaf(sv, w,  acc[bi]);
      accv[bi] = fmaf(sv, vw, accv[bi]);
    }
  }
  float vw2 = Vw2[n];
  #pragma unroll
  for(int bi=0;bi<4;bi++){
    g_sW1[(b0+bi)*EM + n] = acc[bi];
    red[bi][n] = fmaxf(accv[bi], 0.f) * vw2;
  }
  __syncthreads();
  int w = n >> 5, l = n & 31;
  if (w < 4){
    float s = 0.f;
    #pragma unroll
    for(int t=0;t<8;t++) s += red[w][l + t*32];
    #pragma unroll
    for(int off=16; off>0; off>>=1) s += __shfl_xor_sync(0xFFFFFFFFu, s, off);
    if (l == 0) g_v[b0 + w] = s + Vb2[0];
  }
}

// ============ K2: RNG + perms + prefix layer-1 -> A fragments (f32x2 + packed cvt) ============
__global__ void __launch_bounds__(256) k2_layer1(const float* __restrict__ qs,
                                                 const float* __restrict__ W1){
  const int b = blockIdx.x;
  const int tid = threadIdx.x;
  __shared__ int   s_inv[SS][AA];
  __shared__ float s_rqT[2048];  // [(sgrp*8+j)*16+na][sl(4)]

  if(tid < SS){
    int s = tid;
    unsigned base = (unsigned)((b*SS + s)*AA);
    float u[AA];
    #pragma unroll
    for(int a=0;a<AA;a++){
      unsigned g = base + a;
      uint32_t o0, o1;
      threefry2x32(0u, g, o0, o1);
      u[a] = bits_to_unit(o0 ^ o1);
    }
    int ord[AA];
    #pragma unroll
    for(int i=0;i<AA;i++) ord[i]=i;
    for(int i=1;i<AA;i++){
      int oi = ord[i]; float ku = u[oi]; int j=i;
      while(j>0 && u[ord[j-1]] > ku){ ord[j]=ord[j-1]; j--; }
      ord[j]=oi;
    }
    #pragma unroll
    for(int r=0;r<AA;r++) s_inv[s][ord[r]] = r;
    #pragma unroll
    for(int i=0;i<AA;i++) g_pos[base + i] = (unsigned char)ord[i];
  }
  __syncthreads();
  // stage q transposed: s_rqT[((sgrp*8+j)*16+na)*4 + sl] = qs[b, inv[sgrp*4+sl][j], na]
  for(int e=tid; e<2048; e+=256){
    int sl = e & 3;
    int na = (e >> 2) & 15;
    int j  = (e >> 6) & 7;
    int sg = e >> 9;
    int s  = sg*4 + sl;
    s_rqT[e] = qs[b*(AA*NACT) + s_inv[s][j]*NACT + na];
  }
  __syncthreads();

  const int sgrp = tid >> 6;       // 4 s-slots per group
  const int cg   = tid & 63;
  const int kblk = cg >> 2;
  const int kp   = cg & 3;
  const int c0   = kblk*16 + kp*2;

  // acc[sl][pair]: pair0 = cols (c0,c0+1), pair1 = cols (c0+8,c0+9)
  ull acc[4][2];
  {
    ull a01 = *(const ull*)&g_sW1[b*EM + c0];
    ull a89 = *(const ull*)&g_sW1[b*EM + c0 + 8];
    #pragma unroll
    for(int sl=0;sl<4;sl++){ acc[sl][0]=a01; acc[sl][1]=a89; }
  }

  for(int j=0;j<AA;j++){
    #pragma unroll
    for(int na=0;na<NACT;na++){
      const float* wr = &W1[(SD + j*NACT + na)*EM + c0];
      ull w01 = *(const ull*)wr;
      ull w89 = *(const ull*)(wr + 8);
      float4 q4 = *(const float4*)&s_rqT[((sgrp*8 + j)*16 + na)*4];
      ull q;
      q = pack2(q4.x); fma2(acc[0][0],q,w01); fma2(acc[0][1],q,w89);
      q = pack2(q4.y); fma2(acc[1][0],q,w01); fma2(acc[1][1],q,w89);
      q = pack2(q4.z); fma2(acc[2][0],q,w01); fma2(acc[2][1],q,w89);
      q = pack2(q4.w); fma2(acc[3][0],q,w01); fma2(acc[3][1],q,w89);
    }
    const int lane = j*4 + kp;
    #pragma unroll
    for(int p=0;p<2;p++){
      int mblk = sgrp*2 + p;
      float2 x0 = unpack2(acc[2*p][0]);    // row r,   cols c0,c0+1
      float2 x8 = unpack2(acc[2*p][1]);    // row r,   cols c0+8,c0+9
      float2 y0 = unpack2(acc[2*p+1][0]);  // row r+8, cols c0,c0+1
      float2 y8 = unpack2(acc[2*p+1][1]);  // row r+8, cols c0+8,c0+9
      uint4 hv, lv;
      split2(fmaxf(x0.x,0.f), fmaxf(x0.y,0.f), hv.x, lv.x);
      split2(fmaxf(y0.x,0.f), fmaxf(y0.y,0.f), hv.y, lv.y);
      split2(fmaxf(x8.x,0.f), fmaxf(x8.y,0.f), hv.z, lv.z);
      split2(fmaxf(y8.x,0.f), fmaxf(y8.y,0.f), hv.w, lv.w);
      size_t aidx = ((((size_t)b*8 + mblk)*16 + kblk)*32 + lane)*4;
      *(uint4*)&g_Ah[aidx] = hv;
      *(uint4*)&g_Al[aidx] = lv;
    }
  }
}

// ============ K3: HMMA GEMM2 + fused shapley output ============
__global__ void __launch_bounds__(512,1) k3_mma(const float* __restrict__ b2,
                  const float* __restrict__ W3, const float* __restrict__ b3,
                  float* __restrict__ out){
  __shared__ uint32_t sB[2][2][2048];
  __shared__ float b2s[256], w3s[256];
  __shared__ float sred[128][9];
  __shared__ float advs[128];
  __shared__ unsigned char poss[128];
  const int tid  = threadIdx.x;
  const int lane = tid & 31;
  const int warp = tid >> 5;
  const int mblk = warp & 7;
  const int nh   = warp >> 3;
  const int b    = blockIdx.x;

  if (tid < 256){ b2s[tid] = b2[tid]; w3s[tid] = W3[tid]; }
  if (tid >= 256 && tid < 384) poss[tid-256] = g_pos[b*128 + (tid-256)];
  {
    uint4 h = *(const uint4*)&g_Bh[tid*4];
    uint4 l = *(const uint4*)&g_Bl[tid*4];
    *(uint4*)&sB[0][0][tid*4] = h;
    *(uint4*)&sB[0][1][tid*4] = l;
  }

  float d[16][4];
  #pragma unroll
  for(int i=0;i<16;i++){ d[i][0]=0.f; d[i][1]=0.f; d[i][2]=0.f; d[i][3]=0.f; }

  uint32_t ah[4], al[4];
  {
    size_t a0 = ((((size_t)b*8 + mblk)*16 + 0)*32 + lane)*4;
    *(uint4*)ah = *(const uint4*)&g_Ah[a0];
    *(uint4*)al = *(const uint4*)&g_Al[a0];
  }
  __syncthreads();

  for(int kb=0; kb<16; kb++){
    uint4 nh4, nl4;
    uint32_t ahn[4], aln[4];
    if (kb < 15){
      nh4 = *(const uint4*)&g_Bh[(kb+1)*2048 + tid*4];
      nl4 = *(const uint4*)&g_Bl[(kb+1)*2048 + tid*4];
      size_t an = ((((size_t)b*8 + mblk)*16 + (kb+1))*32 + lane)*4;
      *(uint4*)ahn = *(const uint4*)&g_Ah[an];
      *(uint4*)aln = *(const uint4*)&g_Al[an];
    }
    const uint32_t* curh = sB[kb&1][0];
    const uint32_t* curl = sB[kb&1][1];
    #pragma unroll
    for(int nb=0; nb<16; nb++){
      int ng  = nh*16 + nb;
      int off = (ng*32 + lane)*2;
      uint2 bh = *(const uint2*)&curh[off];
      uint2 bl = *(const uint2*)&curl[off];
      mma16816(d[nb], ah, bh.x, bh.y);
      mma16816(d[nb], al, bh.x, bh.y);
      mma16816(d[nb], ah, bl.x, bl.y);
    }
    if (kb < 15){
      *(uint4*)&sB[(kb+1)&1][0][tid*4] = nh4;
      *(uint4*)&sB[(kb+1)&1][1][tid*4] = nl4;
      #pragma unroll
      for(int i=0;i<4;i++){ ah[i]=ahn[i]; al[i]=aln[i]; }
    }
    __syncthreads();
  }

  // epilogue: relu(d + b2) dot W3
  float p0 = 0.f, p1 = 0.f;
  #pragma unroll
  for(int nb=0; nb<16; nb++){
    int c0 = (nh*16 + nb)*8 + (lane&3)*2;
    float w0 = w3s[c0], w1 = w3s[c0+1];
    float bb0 = b2s[c0], bb1 = b2s[c0+1];
    p0 += fmaxf(d[nb][0]+bb0, 0.f)*w0 + fmaxf(d[nb][1]+bb1, 0.f)*w1;
    p1 += fmaxf(d[nb][2]+bb0, 0.f)*w0 + fmaxf(d[nb][3]+bb1, 0.f)*w1;
  }
  p0 += __shfl_xor_sync(0xFFFFFFFFu, p0, 1);
  p0 += __shfl_xor_sync(0xFFFFFFFFu, p0, 2);
  p1 += __shfl_xor_sync(0xFFFFFFFFu, p1, 1);
  p1 += __shfl_xor_sync(0xFFFFFFFFu, p1, 2);
  if ((lane & 3) == 0){
    int r0 = mblk*16 + (lane>>2);
    sred[r0  ][nh] = p0;
    sred[r0+8][nh] = p1;
  }
  __syncthreads();
  if (tid < 128){
    advs[tid] = b3[0] + sred[tid][0] + sred[tid][1];
  }
  __syncthreads();
  if (tid < 8){
    float sum = 0.f;
    #pragma unroll
    for(int s=0;s<SS;s++){
      sum += advs[s*8 + (int)poss[s*8 + tid]];
    }
    out[b*8 + tid] = g_v[b] + sum * (1.0f/16.0f);
  }
}

extern "C" void kernel_launch(void* const* d_in, const int* in_sizes, int n_in,
                              void* d_out, int out_size){
  const float* states   = (const float*)d_in[0];
  const float* agent_qs = (const float*)d_in[1];
  const float* W1  = (const float*)d_in[2];
  const float* b1  = (const float*)d_in[3];
  const float* W2  = (const float*)d_in[4];
  const float* b2  = (const float*)d_in[5];
  const float* W3  = (const float*)d_in[6];
  const float* b3  = (const float*)d_in[7];
  const float* Vw1 = (const float*)d_in[8];
  const float* Vb1 = (const float*)d_in[9];
  const float* Vw2 = (const float*)d_in[10];
  const float* Vb2 = (const float*)d_in[11];
  float* out = (float*)d_out;

  k0_prepW2<<<128, 256>>>(W2);
  k1_state <<<NB/4, 256>>>(states, W1, b1, Vw1, Vb1, Vw2, Vb2);
  k2_layer1<<<NB, 256>>>(agent_qs, W1);
  k3_mma   <<<NB, 512>>>(b2, W3, b3, out);
}

// round 10
// speedup vs baseline: 1.2459x; 1.2459x over previous
#include <cuda_runtime.h>
#include <cuda_bf16.h>
#include <stdint.h>

typedef unsigned long long ull;

#define NB   1024
#define SS   16
#define AA   8
#define NACT 16
#define SD   256
#define EM   256
#define NROWS (NB*SS*AA)   // 131072

// ---------------- device scratch ----------------
__device__ float g_sW1[NB*EM];
__device__ float g_v[NB];
__device__ unsigned char g_pos[NROWS];
// h1 A-fragments: [b][mblk(8)][kblk(16)][lane(32)][reg(4)] u32, hi and lo
__device__ uint32_t g_Ah[(size_t)NB*8*16*32*4];
__device__ uint32_t g_Al[(size_t)NB*8*16*32*4];
// W2 B-fragments interleaved: [kblk(16)][nblk(32)][lane(32)][{bh0,bh1,bl0,bl1}]
__device__ uint32_t g_B[16*32*32*4];

// ---------------- threefry2x32 (JAX exact, key(42)) ----------------
__device__ __forceinline__ uint32_t rotl(uint32_t x, int r){ return (x<<r)|(x>>(32-r)); }
__device__ __forceinline__ void threefry2x32(uint32_t c0, uint32_t c1, uint32_t &o0, uint32_t &o1){
  const uint32_t k0 = 0u, k1v = 42u, k2 = 0u ^ 42u ^ 0x1BD11BDAu;
  uint32_t x0 = c0 + k0;
  uint32_t x1 = c1 + k1v;
#define TF_R(rot) { x0 += x1; x1 = rotl(x1, rot); x1 ^= x0; }
  TF_R(13) TF_R(15) TF_R(26) TF_R(6)
  x0 += k1v; x1 += k2 + 1u;
  TF_R(17) TF_R(29) TF_R(16) TF_R(24)
  x0 += k2;  x1 += k0 + 2u;
  TF_R(13) TF_R(15) TF_R(26) TF_R(6)
  x0 += k0;  x1 += k1v + 3u;
  TF_R(17) TF_R(29) TF_R(16) TF_R(24)
  x0 += k1v; x1 += k2 + 4u;
  TF_R(13) TF_R(15) TF_R(26) TF_R(6)
  x0 += k2;  x1 += k0 + 5u;
#undef TF_R
  o0 = x0; o1 = x1;
}
__device__ __forceinline__ float bits_to_unit(uint32_t bits){
  return __uint_as_float(0x3f800000u | (bits >> 9)) - 1.0f;
}

// ---------------- packed helpers ----------------
__device__ __forceinline__ ull pack2(float x){
  ull r; unsigned u = __float_as_uint(x);
  asm("mov.b64 %0, {%1,%1};" : "=l"(r) : "r"(u));
  return r;
}
__device__ __forceinline__ void fma2(ull& d, ull a, ull b){
  asm("fma.rn.f32x2 %0, %1, %2, %0;" : "+l"(d) : "l"(a), "l"(b));
}
__device__ __forceinline__ float2 unpack2(ull v){
  unsigned lo, hi; asm("mov.b64 {%0,%1}, %2;" : "=r"(lo), "=r"(hi) : "l"(v));
  return make_float2(__uint_as_float(lo), __uint_as_float(hi));
}
__device__ __forceinline__ uint32_t pack_bf16x2(float v0, float v1){
  uint32_t r;
  asm("cvt.rn.bf16x2.f32 %0, %1, %2;" : "=r"(r) : "f"(v1), "f"(v0));
  return r;
}
__device__ __forceinline__ void split2(float v0, float v1, uint32_t &h, uint32_t &l){
  h = pack_bf16x2(v0, v1);
  float h0 = __uint_as_float(h << 16);
  float h1 = __uint_as_float(h & 0xFFFF0000u);
  l = pack_bf16x2(v0 - h0, v1 - h1);
}
__device__ __forceinline__ void split_bf16(float v, uint32_t &h, uint32_t &l){
  __nv_bfloat16 hb = __float2bfloat16(v);
  float lf = v - __bfloat162float(hb);
  __nv_bfloat16 lb = __float2bfloat16(lf);
  h = (uint32_t)__bfloat16_as_ushort(hb);
  l = (uint32_t)__bfloat16_as_ushort(lb);
}

__device__ __forceinline__ void mma16816(float* d, const uint32_t* a, uint32_t b0, uint32_t b1){
  asm volatile("mma.sync.aligned.m16n8k16.row.col.f32.bf16.bf16.f32 "
    "{%0,%1,%2,%3}, {%4,%5,%6,%7}, {%8,%9}, {%0,%1,%2,%3};"
    : "+f"(d[0]),"+f"(d[1]),"+f"(d[2]),"+f"(d[3])
    : "r"(a[0]),"r"(a[1]),"r"(a[2]),"r"(a[3]), "r"(b0),"r"(b1));
}

// ============ K0: W2 -> interleaved B fragments ============
__global__ void k0_prepW2(const float* __restrict__ W2){
  int idx = blockIdx.x*256 + threadIdx.x;   // 32768
  int kp = idx >> 8, n = idx & 255;
  int k = kp*2;
  float v0 = W2[k*EM + n];
  float v1 = W2[(k+1)*EM + n];
  uint32_t h0,l0,h1,l1;
  split_bf16(v0,h0,l0); split_bf16(v1,h1,l1);
  uint32_t hi = h0 | (h1<<16);
  uint32_t lo = l0 | (l1<<16);
  int kblk = kp>>3;
  int reg  = (kp>>2)&1;
  int lane = (n&7)*4 + (kp&3);
  int nblk = n>>3;
  int base = ((kblk*32+nblk)*32+lane)*4;
  g_B[base + reg]     = hi;
  g_B[base + 2 + reg] = lo;
}

// ============ K1: per-b state terms, 4 b per CTA ============
__global__ void __launch_bounds__(256) k1_state(const float* __restrict__ st,
                         const float* __restrict__ W1,
                         const float* __restrict__ b1, const float* __restrict__ Vw1,
                         const float* __restrict__ Vb1, const float* __restrict__ Vw2,
                         const float* __restrict__ Vb2){
  const int b0 = blockIdx.x * 4;
  const int n  = threadIdx.x;
  __shared__ float s_st[4][SD];
  __shared__ float red[4][EM];
  #pragma unroll
  for(int bi=0;bi<4;bi++) s_st[bi][n] = st[(b0+bi)*SD + n];
  __syncthreads();
  float acc[4], accv[4];
  float bb1 = b1[n], vbb = Vb1[n];
  #pragma unroll
  for(int bi=0;bi<4;bi++){ acc[bi]=bb1; accv[bi]=vbb; }
  #pragma unroll 4
  for(int k=0;k<SD;k++){
    float w  = W1 [k*EM + n];
    float vw = Vw1[k*EM + n];
    #pragma unroll
    for(int bi=0;bi<4;bi++){
      float sv = s_st[bi][k];
      acc[bi]  = fmaf(sv, w,  acc[bi]);
      accv[bi] = fmaf(sv, vw, accv[bi]);
    }
  }
  float vw2 = Vw2[n];
  #pragma unroll
  for(int bi=0;bi<4;bi++){
    g_sW1[(b0+bi)*EM + n] = acc[bi];
    red[bi][n] = fmaxf(accv[bi], 0.f) * vw2;
  }
  __syncthreads();
  int w = n >> 5, l = n & 31;
  if (w < 4){
    float s = 0.f;
    #pragma unroll
    for(int t=0;t<8;t++) s += red[w][l + t*32];
    #pragma unroll
    for(int off=16; off>0; off>>=1) s += __shfl_xor_sync(0xFFFFFFFFu, s, off);
    if (l == 0) g_v[b0 + w] = s + Vb2[0];
  }
}

// ============ K2: RNG + perms + prefix layer-1 -> A fragments (f32x2) ============
__global__ void __launch_bounds__(256) k2_layer1(const float* __restrict__ qs,
                                                 const float* __restrict__ W1){
  const int b = blockIdx.x;
  const int tid = threadIdx.x;
  __shared__ int   s_inv[SS][AA];
  __shared__ float s_rqT[2048];  // [(sgrp*8+j)*16+na][sl(4)]

  if(tid < SS){
    int s = tid;
    unsigned base = (unsigned)((b*SS + s)*AA);
    float u[AA];
    #pragma unroll
    for(int a=0;a<AA;a++){
      unsigned g = base + a;
      uint32_t o0, o1;
      threefry2x32(0u, g, o0, o1);
      u[a] = bits_to_unit(o0 ^ o1);
    }
    int ord[AA];
    #pragma unroll
    for(int i=0;i<AA;i++) ord[i]=i;
    for(int i=1;i<AA;i++){
      int oi = ord[i]; float ku = u[oi]; int j=i;
      while(j>0 && u[ord[j-1]] > ku){ ord[j]=ord[j-1]; j--; }
      ord[j]=oi;
    }
    #pragma unroll
    for(int r=0;r<AA;r++) s_inv[s][ord[r]] = r;
    #pragma unroll
    for(int i=0;i<AA;i++) g_pos[base + i] = (unsigned char)ord[i];
  }
  __syncthreads();
  for(int e=tid; e<2048; e+=256){
    int sl = e & 3;
    int na = (e >> 2) & 15;
    int j  = (e >> 6) & 7;
    int sg = e >> 9;
    int s  = sg*4 + sl;
    s_rqT[e] = qs[b*(AA*NACT) + s_inv[s][j]*NACT + na];
  }
  __syncthreads();

  const int sgrp = tid >> 6;
  const int cg   = tid & 63;
  const int kblk = cg >> 2;
  const int kp   = cg & 3;
  const int c0   = kblk*16 + kp*2;

  ull acc[4][2];
  {
    ull a01 = *(const ull*)&g_sW1[b*EM + c0];
    ull a89 = *(const ull*)&g_sW1[b*EM + c0 + 8];
    #pragma unroll
    for(int sl=0;sl<4;sl++){ acc[sl][0]=a01; acc[sl][1]=a89; }
  }

  for(int j=0;j<AA;j++){
    #pragma unroll
    for(int na=0;na<NACT;na++){
      const float* wr = &W1[(SD + j*NACT + na)*EM + c0];
      ull w01 = *(const ull*)wr;
      ull w89 = *(const ull*)(wr + 8);
      float4 q4 = *(const float4*)&s_rqT[((sgrp*8 + j)*16 + na)*4];
      ull q;
      q = pack2(q4.x); fma2(acc[0][0],q,w01); fma2(acc[0][1],q,w89);
      q = pack2(q4.y); fma2(acc[1][0],q,w01); fma2(acc[1][1],q,w89);
      q = pack2(q4.z); fma2(acc[2][0],q,w01); fma2(acc[2][1],q,w89);
      q = pack2(q4.w); fma2(acc[3][0],q,w01); fma2(acc[3][1],q,w89);
    }
    const int lane = j*4 + kp;
    #pragma unroll
    for(int p=0;p<2;p++){
      int mblk = sgrp*2 + p;
      float2 x0 = unpack2(acc[2*p][0]);
      float2 x8 = unpack2(acc[2*p][1]);
      float2 y0 = unpack2(acc[2*p+1][0]);
      float2 y8 = unpack2(acc[2*p+1][1]);
      uint4 hv, lv;
      split2(fmaxf(x0.x,0.f), fmaxf(x0.y,0.f), hv.x, lv.x);
      split2(fmaxf(y0.x,0.f), fmaxf(y0.y,0.f), hv.y, lv.y);
      split2(fmaxf(x8.x,0.f), fmaxf(x8.y,0.f), hv.z, lv.z);
      split2(fmaxf(y8.x,0.f), fmaxf(y8.y,0.f), hv.w, lv.w);
      size_t aidx = ((((size_t)b*8 + mblk)*16 + kblk)*32 + lane)*4;
      *(uint4*)&g_Ah[aidx] = hv;
      *(uint4*)&g_Al[aidx] = lv;
    }
  }
}

// ============ K3: HMMA GEMM2 (R5 warp layout + interleaved B) + fused output ============
__global__ void __launch_bounds__(512,1) k3_mma(const float* __restrict__ b2,
                  const float* __restrict__ W3, const float* __restrict__ b3,
                  float* __restrict__ out){
  __shared__ uint32_t sB[2][4096];   // interleaved {bh0,bh1,bl0,bl1} per (ng,lane)
  __shared__ float b2s[256], w3s[256];
  __shared__ float sred[128][9];
  __shared__ float advs[128];
  __shared__ unsigned char poss[128];
  const int tid  = threadIdx.x;
  const int lane = tid & 31;
  const int warp = tid >> 5;
  const int mblk = warp & 7;
  const int nh   = warp >> 3;
  const int b    = blockIdx.x;

  if (tid < 256){ b2s[tid] = b2[tid]; w3s[tid] = W3[tid]; }
  if (tid >= 256 && tid < 384) poss[tid-256] = g_pos[b*128 + (tid-256)];
  {
    const uint4* src = (const uint4*)g_B;
    uint4* dst = (uint4*)sB[0];
    dst[tid*2]   = src[tid*2];
    dst[tid*2+1] = src[tid*2+1];
  }

  float d[16][4];
  #pragma unroll
  for(int i=0;i<16;i++){ d[i][0]=0.f; d[i][1]=0.f; d[i][2]=0.f; d[i][3]=0.f; }

  uint32_t ah[4], al[4];
  {
    size_t a0 = ((((size_t)b*8 + mblk)*16 + 0)*32 + lane)*4;
    *(uint4*)ah = *(const uint4*)&g_Ah[a0];
    *(uint4*)al = *(const uint4*)&g_Al[a0];
  }
  __syncthreads();

  for(int kb=0; kb<16; kb++){
    uint4 bs0, bs1;
    uint32_t ahn[4], aln[4];
    if (kb < 15){
      const uint4* src = (const uint4*)(g_B + (kb+1)*4096);
      bs0 = src[tid*2];
      bs1 = src[tid*2+1];
      size_t an = ((((size_t)b*8 + mblk)*16 + (kb+1))*32 + lane)*4;
      *(uint4*)ahn = *(const uint4*)&g_Ah[an];
      *(uint4*)aln = *(const uint4*)&g_Al[an];
    }
    const uint32_t* cur = sB[kb&1];
    #pragma unroll
    for(int nb=0; nb<16; nb++){
      int ng = nh*16 + nb;
      uint4 bb = *(const uint4*)&cur[(ng*32 + lane)*4];
      mma16816(d[nb], ah, bb.x, bb.y);   // ah*bh
      mma16816(d[nb], al, bb.x, bb.y);   // al*bh
      mma16816(d[nb], ah, bb.z, bb.w);   // ah*bl
    }
    if (kb < 15){
      uint4* dst = (uint4*)sB[(kb+1)&1];
      dst[tid*2]   = bs0;
      dst[tid*2+1] = bs1;
      #pragma unroll
      for(int i=0;i<4;i++){ ah[i]=ahn[i]; al[i]=aln[i]; }
    }
    __syncthreads();
  }

  // epilogue: relu(d + b2) dot W3
  float p0 = 0.f, p1 = 0.f;
  #pragma unroll
  for(int nb=0; nb<16; nb++){
    int c0 = (nh*16 + nb)*8 + (lane&3)*2;
    float w0 = w3s[c0], w1 = w3s[c0+1];
    float bb0 = b2s[c0], bb1 = b2s[c0+1];
    p0 += fmaxf(d[nb][0]+bb0, 0.f)*w0 + fmaxf(d[nb][1]+bb1, 0.f)*w1;
    p1 += fmaxf(d[nb][2]+bb0, 0.f)*w0 + fmaxf(d[nb][3]+bb1, 0.f)*w1;
  }
  p0 += __shfl_xor_sync(0xFFFFFFFFu, p0, 1);
  p0 += __shfl_xor_sync(0xFFFFFFFFu, p0, 2);
  p1 += __shfl_xor_sync(0xFFFFFFFFu, p1, 1);
  p1 += __shfl_xor_sync(0xFFFFFFFFu, p1, 2);
  if ((lane & 3) == 0){
    int r0 = mblk*16 + (lane>>2);
    sred[r0  ][nh] = p0;
    sred[r0+8][nh] = p1;
  }
  __syncthreads();
  if (tid < 128){
    advs[tid] = b3[0] + sred[tid][0] + sred[tid][1];
  }
  __syncthreads();
  if (tid < 8){
    float sum = 0.f;
    #pragma unroll
    for(int s=0;s<SS;s++){
      sum += advs[s*8 + (int)poss[s*8 + tid]];
    }
    out[b*8 + tid] = g_v[b] + sum * (1.0f/16.0f);
  }
}

extern "C" void kernel_launch(void* const* d_in, const int* in_sizes, int n_in,
                              void* d_out, int out_size){
  const float* states   = (const float*)d_in[0];
  const float* agent_qs = (const float*)d_in[1];
  const float* W1  = (const float*)d_in[2];
  const float* b1  = (const float*)d_in[3];
  const float* W2  = (const float*)d_in[4];
  const float* b2  = (const float*)d_in[5];
  const float* W3  = (const float*)d_in[6];
  const float* b3  = (const float*)d_in[7];
  const float* Vw1 = (const float*)d_in[8];
  const float* Vb1 = (const float*)d_in[9];
  const float* Vw2 = (const float*)d_in[10];
  const float* Vb2 = (const float*)d_in[11];
  float* out = (float*)d_out;

  k0_prepW2<<<128, 256>>>(W2);
  k1_state <<<NB/4, 256>>>(states, W1, b1, Vw1, Vb1, Vw2, Vb2);
  k2_layer1<<<NB, 256>>>(agent_qs, W1);
  k3_mma   <<<NB, 512>>>(b2, W3, b3, out);
}

// round 11
// speedup vs baseline: 1.5985x; 1.2831x over previous
#include <cuda_runtime.h>
#include <cuda_bf16.h>
#include <stdint.h>

typedef unsigned long long ull;

#define NB   1024
#define SS   16
#define AA   8
#define NACT 16
#define SD   256
#define EM   256

// ---------------- device scratch ----------------
__device__ float g_sW1[NB*EM];
__device__ float g_v[NB];
// W2 B-fragments: [kblk(16)][nblk(32)][lane(32)][reg(2)] u32 (R5/R8 layout, split hi/lo)
__device__ uint32_t g_Bh[16*32*32*2];
__device__ uint32_t g_Bl[16*32*32*2];

// ---------------- threefry2x32 (JAX exact, key(42)) ----------------
__device__ __forceinline__ uint32_t rotl(uint32_t x, int r){ return (x<<r)|(x>>(32-r)); }
__device__ __forceinline__ void threefry2x32(uint32_t c0, uint32_t c1, uint32_t &o0, uint32_t &o1){
  const uint32_t k0 = 0u, k1v = 42u, k2 = 0u ^ 42u ^ 0x1BD11BDAu;
  uint32_t x0 = c0 + k0;
  uint32_t x1 = c1 + k1v;
#define TF_R(rot) { x0 += x1; x1 = rotl(x1, rot); x1 ^= x0; }
  TF_R(13) TF_R(15) TF_R(26) TF_R(6)
  x0 += k1v; x1 += k2 + 1u;
  TF_R(17) TF_R(29) TF_R(16) TF_R(24)
  x0 += k2;  x1 += k0 + 2u;
  TF_R(13) TF_R(15) TF_R(26) TF_R(6)
  x0 += k0;  x1 += k1v + 3u;
  TF_R(17) TF_R(29) TF_R(16) TF_R(24)
  x0 += k1v; x1 += k2 + 4u;
  TF_R(13) TF_R(15) TF_R(26) TF_R(6)
  x0 += k2;  x1 += k0 + 5u;
#undef TF_R
  o0 = x0; o1 = x1;
}
__device__ __forceinline__ float bits_to_unit(uint32_t bits){
  return __uint_as_float(0x3f800000u | (bits >> 9)) - 1.0f;
}

// ---------------- packed helpers ----------------
__device__ __forceinline__ ull pack2(float x){
  ull r; unsigned u = __float_as_uint(x);
  asm("mov.b64 %0, {%1,%1};" : "=l"(r) : "r"(u));
  return r;
}
__device__ __forceinline__ void fma2(ull& d, ull a, ull b){
  asm("fma.rn.f32x2 %0, %1, %2, %0;" : "+l"(d) : "l"(a), "l"(b));
}
__device__ __forceinline__ float2 unpack2(ull v){
  unsigned lo, hi; asm("mov.b64 {%0,%1}, %2;" : "=r"(lo), "=r"(hi) : "l"(v));
  return make_float2(__uint_as_float(lo), __uint_as_float(hi));
}
__device__ __forceinline__ uint32_t pack_bf16x2(float v0, float v1){
  uint32_t r;
  asm("cvt.rn.bf16x2.f32 %0, %1, %2;" : "=r"(r) : "f"(v1), "f"(v0));
  return r;
}
__device__ __forceinline__ void split2(float v0, float v1, uint32_t &h, uint32_t &l){
  h = pack_bf16x2(v0, v1);
  float h0 = __uint_as_float(h << 16);
  float h1 = __uint_as_float(h & 0xFFFF0000u);
  l = pack_bf16x2(v0 - h0, v1 - h1);
}
__device__ __forceinline__ void split_bf16(float v, uint32_t &h, uint32_t &l){
  __nv_bfloat16 hb = __float2bfloat16(v);
  float lf = v - __bfloat162float(hb);
  __nv_bfloat16 lb = __float2bfloat16(lf);
  h = (uint32_t)__bfloat16_as_ushort(hb);
  l = (uint32_t)__bfloat16_as_ushort(lb);
}

__device__ __forceinline__ void mma16816(float* d, const uint32_t* a, uint32_t b0, uint32_t b1){
  asm volatile("mma.sync.aligned.m16n8k16.row.col.f32.bf16.bf16.f32 "
    "{%0,%1,%2,%3}, {%4,%5,%6,%7}, {%8,%9}, {%0,%1,%2,%3};"
    : "+f"(d[0]),"+f"(d[1]),"+f"(d[2]),"+f"(d[3])
    : "r"(a[0]),"r"(a[1]),"r"(a[2]),"r"(a[3]), "r"(b0),"r"(b1));
}

// ============ K0: W2 -> B fragments (split hi/lo, R8 layout) ============
__global__ void k0_prepW2(const float* __restrict__ W2){
  int idx = blockIdx.x*256 + threadIdx.x;   // 32768
  int kp = idx >> 8, n = idx & 255;
  int k = kp*2;
  float v0 = W2[k*EM + n];
  float v1 = W2[(k+1)*EM + n];
  uint32_t h0,l0,h1,l1;
  split_bf16(v0,h0,l0); split_bf16(v1,h1,l1);
  uint32_t hi = h0 | (h1<<16);
  uint32_t lo = l0 | (l1<<16);
  int kblk = kp>>3;
  int reg  = (kp>>2)&1;
  int lane = (n&7)*4 + (kp&3);
  int nblk = n>>3;
  int bidx = ((kblk*32+nblk)*32+lane)*2 + reg;
  g_Bh[bidx] = hi;
  g_Bl[bidx] = lo;
}

// ============ K1: per-b state terms, 4 b per CTA ============
__global__ void __launch_bounds__(256) k1_state(const float* __restrict__ st,
                         const float* __restrict__ W1,
                         const float* __restrict__ b1, const float* __restrict__ Vw1,
                         const float* __restrict__ Vb1, const float* __restrict__ Vw2,
                         const float* __restrict__ Vb2){
  const int b0 = blockIdx.x * 4;
  const int n  = threadIdx.x;
  __shared__ float s_st[4][SD];
  __shared__ float red[4][EM];
  #pragma unroll
  for(int bi=0;bi<4;bi++) s_st[bi][n] = st[(b0+bi)*SD + n];
  __syncthreads();
  float acc[4], accv[4];
  float bb1 = b1[n], vbb = Vb1[n];
  #pragma unroll
  for(int bi=0;bi<4;bi++){ acc[bi]=bb1; accv[bi]=vbb; }
  #pragma unroll 4
  for(int k=0;k<SD;k++){
    float w  = W1 [k*EM + n];
    float vw = Vw1[k*EM + n];
    #pragma unroll
    for(int bi=0;bi<4;bi++){
      float sv = s_st[bi][k];
      acc[bi]  = fmaf(sv, w,  acc[bi]);
      accv[bi] = fmaf(sv, vw, accv[bi]);
    }
  }
  float vw2 = Vw2[n];
  #pragma unroll
  for(int bi=0;bi<4;bi++){
    g_sW1[(b0+bi)*EM + n] = acc[bi];
    red[bi][n] = fmaxf(accv[bi], 0.f) * vw2;
  }
  __syncthreads();
  int w = n >> 5, l = n & 31;
  if (w < 4){
    float s = 0.f;
    #pragma unroll
    for(int t=0;t<8;t++) s += red[w][l + t*32];
    #pragma unroll
    for(int off=16; off>0; off>>=1) s += __shfl_xor_sync(0xFFFFFFFFu, s, off);
    if (l == 0) g_v[b0 + w] = s + Vb2[0];
  }
}

// ============ Fused: RNG + layer-1 (A frags in smem) + HMMA GEMM2 + shapley out ============
// dynamic smem layout (bytes)
#define S_AH  0                 // 65536: A hi frags [mblk*16+kblk][lane][reg]
#define S_AL  65536             // 65536: A lo frags
#define S_BH  131072            // 16384: B hi double-buffer [buf][2048]
#define S_BL  147456            // 16384: B lo
#define S_RQ  163840            // 8192:  q transposed [(sgrp*8+j)*16+na][p(2)]
#define S_B2  172032            // 1024
#define S_W3  173056            // 1024
#define S_RED 174080            // 4608:  sred[128][9]
#define S_ADV 178688            // 512
#define S_POS 179200            // 128
#define S_INV 179328            // 512:   s_inv[16][8] int
#define S_W1  179840            // 32768: W1x row double-buffer [buf][4096 floats]
#define SM_TOT 212608

__global__ void __launch_bounds__(512,1) kfused(const float* __restrict__ qs,
                  const float* __restrict__ W1,
                  const float* __restrict__ b2, const float* __restrict__ W3,
                  const float* __restrict__ b3, float* __restrict__ out){
  extern __shared__ __align__(16) char sm[];
  uint32_t* sAh = (uint32_t*)(sm + S_AH);
  uint32_t* sAl = (uint32_t*)(sm + S_AL);
  uint32_t* sBh = (uint32_t*)(sm + S_BH);
  uint32_t* sBl = (uint32_t*)(sm + S_BL);
  float* rqT = (float*)(sm + S_RQ);
  float* b2s = (float*)(sm + S_B2);
  float* w3s = (float*)(sm + S_W3);
  float (*sred)[9] = (float(*)[9])(sm + S_RED);
  float* advs = (float*)(sm + S_ADV);
  unsigned char* poss = (unsigned char*)(sm + S_POS);
  int (*s_inv)[AA] = (int(*)[AA])(sm + S_INV);
  float* sW1x = (float*)(sm + S_W1);   // [2][4096]

  const int tid = threadIdx.x;
  const int b = blockIdx.x;

  // early staging: B chunk 0, b2/W3, W1x rows for j=0
  {
    uint4 h = *(const uint4*)&g_Bh[tid*4];
    uint4 l = *(const uint4*)&g_Bl[tid*4];
    *(uint4*)&sBh[tid*4] = h;
    *(uint4*)&sBl[tid*4] = l;
  }
  if (tid < 256){ b2s[tid] = b2[tid]; w3s[tid] = W3[tid]; }
  {
    // j=0: rows SD..SD+15 = 4096 floats contiguous
    const uint4* src = (const uint4*)&W1[SD*EM];
    uint4* dst = (uint4*)sW1x;
    dst[tid]       = src[tid];
    dst[tid + 512] = src[tid + 512];
  }

  // RNG + permutations
  if (tid < SS){
    int s = tid;
    unsigned base = (unsigned)((b*SS + s)*AA);
    float u[AA];
    #pragma unroll
    for(int a=0;a<AA;a++){
      uint32_t o0, o1;
      threefry2x32(0u, base + a, o0, o1);
      u[a] = bits_to_unit(o0 ^ o1);
    }
    int ord[AA];
    #pragma unroll
    for(int i=0;i<AA;i++) ord[i]=i;
    for(int i=1;i<AA;i++){
      int oi = ord[i]; float ku = u[oi]; int j=i;
      while(j>0 && u[ord[j-1]] > ku){ ord[j]=ord[j-1]; j--; }
      ord[j]=oi;
    }
    #pragma unroll
    for(int r=0;r<AA;r++) s_inv[s][ord[r]] = r;
    #pragma unroll
    for(int i=0;i<AA;i++) poss[s*8 + i] = (unsigned char)ord[i];
  }
  __syncthreads();
  // stage q transposed: rqT[((sgrp*8+j)*16+na)*2 + p] = qs[b, inv[sgrp*2+p][j], na]
  for(int e=tid; e<2048; e+=512){
    int p  = e & 1;
    int na = (e >> 1) & 15;
    int j  = (e >> 5) & 7;
    int sg = e >> 8;
    int s  = sg*2 + p;
    rqT[e] = qs[b*(AA*NACT) + s_inv[s][j]*NACT + na];
  }
  __syncthreads();

  // ---- layer-1: per-thread (sgrp: 2 s-slots, cg: 4 cols), prefix over j ----
  {
    const int sgrp = tid >> 6;       // 0..7 -> s = sgrp*2 + p
    const int cg   = tid & 63;
    const int kblk = cg >> 2;
    const int kp   = cg & 3;
    const int c0   = kblk*16 + kp*2;

    ull acc[2][2];
    {
      ull a01 = *(const ull*)&g_sW1[b*EM + c0];
      ull a89 = *(const ull*)&g_sW1[b*EM + c0 + 8];
      acc[0][0]=a01; acc[0][1]=a89;
      acc[1][0]=a01; acc[1][1]=a89;
    }

    for(int j=0;j<AA;j++){
      // prefetch W1x rows for j+1 into other buffer
      uint4 w1a, w1b;
      if (j < 7){
        const uint4* src = (const uint4*)&W1[(SD + (j+1)*16)*EM];
        w1a = src[tid];
        w1b = src[tid + 512];
      }
      const float* wbuf = &sW1x[(j&1)*4096];
      #pragma unroll
      for(int na=0;na<NACT;na++){
        ull w01 = *(const ull*)&wbuf[na*256 + c0];
        ull w89 = *(const ull*)&wbuf[na*256 + c0 + 8];
        float2 q2 = *(const float2*)&rqT[((sgrp*8 + j)*16 + na)*2];
        ull q;
        q = pack2(q2.x); fma2(acc[0][0],q,w01); fma2(acc[0][1],q,w89);
        q = pack2(q2.y); fma2(acc[1][0],q,w01); fma2(acc[1][1],q,w89);
      }
      // emit fragment: mblk=sgrp, rows sgrp*16+j (p=0) and +8 (p=1)
      {
        const int lane = j*4 + kp;
        float2 x0 = unpack2(acc[0][0]);
        float2 x8 = unpack2(acc[0][1]);
        float2 y0 = unpack2(acc[1][0]);
        float2 y8 = unpack2(acc[1][1]);
        uint4 hv, lv;
        split2(fmaxf(x0.x,0.f), fmaxf(x0.y,0.f), hv.x, lv.x);
        split2(fmaxf(y0.x,0.f), fmaxf(y0.y,0.f), hv.y, lv.y);
        split2(fmaxf(x8.x,0.f), fmaxf(x8.y,0.f), hv.z, lv.z);
        split2(fmaxf(y8.x,0.f), fmaxf(y8.y,0.f), hv.w, lv.w);
        int aidx = ((sgrp*16 + kblk)*32 + lane)*4;
        *(uint4*)&sAh[aidx] = hv;
        *(uint4*)&sAl[aidx] = lv;
      }
      if (j < 7){
        uint4* dst = (uint4*)&sW1x[((j+1)&1)*4096];
        dst[tid]       = w1a;
        dst[tid + 512] = w1b;
      }
      __syncthreads();
    }
  }
  // fragments + B0 now visible

  // ---- GEMM mainloop (R8 verbatim, A from smem) ----
  const int lane = tid & 31;
  const int warp = tid >> 5;
  const int mblk = warp & 7;
  const int nh   = warp >> 3;

  float d[16][4];
  #pragma unroll
  for(int i=0;i<16;i++){ d[i][0]=0.f; d[i][1]=0.f; d[i][2]=0.f; d[i][3]=0.f; }

  for(int kb=0; kb<16; kb++){
    uint4 nh4, nl4;
    if (kb < 15){
      nh4 = *(const uint4*)&g_Bh[(kb+1)*2048 + tid*4];
      nl4 = *(const uint4*)&g_Bl[(kb+1)*2048 + tid*4];
    }
    uint32_t ah[4], al[4];
    {
      int aidx = ((mblk*16 + kb)*32 + lane)*4;
      *(uint4*)ah = *(const uint4*)&sAh[aidx];
      *(uint4*)al = *(const uint4*)&sAl[aidx];
    }
    const uint32_t* curh = &sBh[(kb&1)*2048];
    const uint32_t* curl = &sBl[(kb&1)*2048];
    #pragma unroll
    for(int nb=0; nb<16; nb++){
      int ng  = nh*16 + nb;
      int off = (ng*32 + lane)*2;
      uint2 bh = *(const uint2*)&curh[off];
      uint2 bl = *(const uint2*)&curl[off];
      mma16816(d[nb], ah, bh.x, bh.y);
      mma16816(d[nb], al, bh.x, bh.y);
      mma16816(d[nb], ah, bl.x, bl.y);
    }
    if (kb < 15){
      *(uint4*)&sBh[((kb+1)&1)*2048 + tid*4] = nh4;
      *(uint4*)&sBl[((kb+1)&1)*2048 + tid*4] = nl4;
    }
    __syncthreads();
  }

  // ---- epilogue: relu(d + b2) dot W3, quad shfl-reduce, fused shapley ----
  float p0 = 0.f, p1 = 0.f;
  #pragma unroll
  for(int nb=0; nb<16; nb++){
    int c0 = (nh*16 + nb)*8 + (lane&3)*2;
    float w0 = w3s[c0], w1 = w3s[c0+1];
    float bb0 = b2s[c0], bb1 = b2s[c0+1];
    p0 += fmaxf(d[nb][0]+bb0, 0.f)*w0 + fmaxf(d[nb][1]+bb1, 0.f)*w1;
    p1 += fmaxf(d[nb][2]+bb0, 0.f)*w0 + fmaxf(d[nb][3]+bb1, 0.f)*w1;
  }
  p0 += __shfl_xor_sync(0xFFFFFFFFu, p0, 1);
  p0 += __shfl_xor_sync(0xFFFFFFFFu, p0, 2);
  p1 += __shfl_xor_sync(0xFFFFFFFFu, p1, 1);
  p1 += __shfl_xor_sync(0xFFFFFFFFu, p1, 2);
  if ((lane & 3) == 0){
    int r0 = mblk*16 + (lane>>2);
    sred[r0  ][nh] = p0;
    sred[r0+8][nh] = p1;
  }
  __syncthreads();
  if (tid < 128){
    advs[tid] = b3[0] + sred[tid][0] + sred[tid][1];
  }
  __syncthreads();
  if (tid < 8){
    float sum = 0.f;
    #pragma unroll
    for(int s=0;s<SS;s++){
      sum += advs[s*8 + (int)poss[s*8 + tid]];
    }
    out[b*8 + tid] = g_v[b] + sum * (1.0f/16.0f);
  }
}

extern "C" void kernel_launch(void* const* d_in, const int* in_sizes, int n_in,
                              void* d_out, int out_size){
  const float* states   = (const float*)d_in[0];
  const float* agent_qs = (const float*)d_in[1];
  const float* W1  = (const float*)d_in[2];
  const float* b1  = (const float*)d_in[3];
  const float* W2  = (const float*)d_in[4];
  const float* b2  = (const float*)d_in[5];
  const float* W3  = (const float*)d_in[6];
  const float* b3  = (const float*)d_in[7];
  const float* Vw1 = (const float*)d_in[8];
  const float* Vb1 = (const float*)d_in[9];
  const float* Vw2 = (const float*)d_in[10];
  const float* Vb2 = (const float*)d_in[11];
  float* out = (float*)d_out;

  static bool attr_set = false;
  if (!attr_set){
    cudaFuncSetAttribute(kfused, cudaFuncAttributeMaxDynamicSharedMemorySize, SM_TOT);
    attr_set = true;
  }

  k0_prepW2<<<128, 256>>>(W2);
  k1_state <<<NB/4, 256>>>(states, W1, b1, Vw1, Vb1, Vw2, Vb2);
  kfused   <<<NB, 512, SM_TOT>>>(agent_qs, W1, b2, W3, b3, out);
}

// round 12
// speedup vs baseline: 1.6516x; 1.0332x over previous
#include <cuda_runtime.h>
#include <cuda_bf16.h>
#include <stdint.h>

typedef unsigned long long ull;

#define NB   1024
#define SS   16
#define AA   8
#define NACT 16
#define SD   256
#define EM   256

// ---------------- device scratch ----------------
__device__ float g_sW1[NB*EM];
__device__ float g_v[NB];
// W2 B-fragments: [kblk(16)][nblk(32)][lane(32)][reg(2)] u32 (split hi/lo)
__device__ uint32_t g_Bh[16*32*32*2];
__device__ uint32_t g_Bl[16*32*32*2];

// ---------------- threefry2x32 (JAX exact, key(42)) ----------------
__device__ __forceinline__ uint32_t rotl(uint32_t x, int r){ return (x<<r)|(x>>(32-r)); }
__device__ __forceinline__ void threefry2x32(uint32_t c0, uint32_t c1, uint32_t &o0, uint32_t &o1){
  const uint32_t k0 = 0u, k1v = 42u, k2 = 0u ^ 42u ^ 0x1BD11BDAu;
  uint32_t x0 = c0 + k0;
  uint32_t x1 = c1 + k1v;
#define TF_R(rot) { x0 += x1; x1 = rotl(x1, rot); x1 ^= x0; }
  TF_R(13) TF_R(15) TF_R(26) TF_R(6)
  x0 += k1v; x1 += k2 + 1u;
  TF_R(17) TF_R(29) TF_R(16) TF_R(24)
  x0 += k2;  x1 += k0 + 2u;
  TF_R(13) TF_R(15) TF_R(26) TF_R(6)
  x0 += k0;  x1 += k1v + 3u;
  TF_R(17) TF_R(29) TF_R(16) TF_R(24)
  x0 += k1v; x1 += k2 + 4u;
  TF_R(13) TF_R(15) TF_R(26) TF_R(6)
  x0 += k2;  x1 += k0 + 5u;
#undef TF_R
  o0 = x0; o1 = x1;
}
__device__ __forceinline__ float bits_to_unit(uint32_t bits){
  return __uint_as_float(0x3f800000u | (bits >> 9)) - 1.0f;
}

// ---------------- packed helpers ----------------
__device__ __forceinline__ ull pack2(float x){
  ull r; unsigned u = __float_as_uint(x);
  asm("mov.b64 %0, {%1,%1};" : "=l"(r) : "r"(u));
  return r;
}
__device__ __forceinline__ void fma2(ull& d, ull a, ull b){
  asm("fma.rn.f32x2 %0, %1, %2, %0;" : "+l"(d) : "l"(a), "l"(b));
}
__device__ __forceinline__ float2 unpack2(ull v){
  unsigned lo, hi; asm("mov.b64 {%0,%1}, %2;" : "=r"(lo), "=r"(hi) : "l"(v));
  return make_float2(__uint_as_float(lo), __uint_as_float(hi));
}
__device__ __forceinline__ uint32_t pack_bf16x2(float v0, float v1){
  uint32_t r;
  asm("cvt.rn.bf16x2.f32 %0, %1, %2;" : "=r"(r) : "f"(v1), "f"(v0));
  return r;
}
__device__ __forceinline__ void split2(float v0, float v1, uint32_t &h, uint32_t &l){
  h = pack_bf16x2(v0, v1);
  float h0 = __uint_as_float(h << 16);
  float h1 = __uint_as_float(h & 0xFFFF0000u);
  l = pack_bf16x2(v0 - h0, v1 - h1);
}
__device__ __forceinline__ void split_bf16(float v, uint32_t &h, uint32_t &l){
  __nv_bfloat16 hb = __float2bfloat16(v);
  float lf = v - __bfloat162float(hb);
  __nv_bfloat16 lb = __float2bfloat16(lf);
  h = (uint32_t)__bfloat16_as_ushort(hb);
  l = (uint32_t)__bfloat16_as_ushort(lb);
}

__device__ __forceinline__ void mma16816(float* d, const uint32_t* a, uint32_t b0, uint32_t b1){
  asm volatile("mma.sync.aligned.m16n8k16.row.col.f32.bf16.bf16.f32 "
    "{%0,%1,%2,%3}, {%4,%5,%6,%7}, {%8,%9}, {%0,%1,%2,%3};"
    : "+f"(d[0]),"+f"(d[1]),"+f"(d[2]),"+f"(d[3])
    : "r"(a[0]),"r"(a[1]),"r"(a[2]),"r"(a[3]), "r"(b0),"r"(b1));
}

// ============ K0: W2 -> B fragments ============
__global__ void k0_prepW2(const float* __restrict__ W2){
  int idx = blockIdx.x*256 + threadIdx.x;   // 32768
  int kp = idx >> 8, n = idx & 255;
  int k = kp*2;
  float v0 = W2[k*EM + n];
  float v1 = W2[(k+1)*EM + n];
  uint32_t h0,l0,h1,l1;
  split_bf16(v0,h0,l0); split_bf16(v1,h1,l1);
  uint32_t hi = h0 | (h1<<16);
  uint32_t lo = l0 | (l1<<16);
  int kblk = kp>>3;
  int reg  = (kp>>2)&1;
  int lane = (n&7)*4 + (kp&3);
  int nblk = n>>3;
  int bidx = ((kblk*32+nblk)*32+lane)*2 + reg;
  g_Bh[bidx] = hi;
  g_Bl[bidx] = lo;
}

// ============ K1: per-b state terms, 4 b per CTA ============
__global__ void __launch_bounds__(256) k1_state(const float* __restrict__ st,
                         const float* __restrict__ W1,
                         const float* __restrict__ b1, const float* __restrict__ Vw1,
                         const float* __restrict__ Vb1, const float* __restrict__ Vw2,
                         const float* __restrict__ Vb2){
  const int b0 = blockIdx.x * 4;
  const int n  = threadIdx.x;
  __shared__ float s_st[4][SD];
  __shared__ float red[4][EM];
  #pragma unroll
  for(int bi=0;bi<4;bi++) s_st[bi][n] = st[(b0+bi)*SD + n];
  __syncthreads();
  float acc[4], accv[4];
  float bb1 = b1[n], vbb = Vb1[n];
  #pragma unroll
  for(int bi=0;bi<4;bi++){ acc[bi]=bb1; accv[bi]=vbb; }
  #pragma unroll 4
  for(int k=0;k<SD;k++){
    float w  = W1 [k*EM + n];
    float vw = Vw1[k*EM + n];
    #pragma unroll
    for(int bi=0;bi<4;bi++){
      float sv = s_st[bi][k];
      acc[bi]  = fmaf(sv, w,  acc[bi]);
      accv[bi] = fmaf(sv, vw, accv[bi]);
    }
  }
  float vw2 = Vw2[n];
  #pragma unroll
  for(int bi=0;bi<4;bi++){
    g_sW1[(b0+bi)*EM + n] = acc[bi];
    red[bi][n] = fmaxf(accv[bi], 0.f) * vw2;
  }
  __syncthreads();
  int w = n >> 5, l = n & 31;
  if (w < 4){
    float s = 0.f;
    #pragma unroll
    for(int t=0;t<8;t++) s += red[w][l + t*32];
    #pragma unroll
    for(int off=16; off>0; off>>=1) s += __shfl_xor_sync(0xFFFFFFFFu, s, off);
    if (l == 0) g_v[b0 + w] = s + Vb2[0];
  }
}

// ============ K_init: out[b,i] = v[b] (atomics accumulate on top) ============
__global__ void kinit_out(float* __restrict__ out){
  int idx = blockIdx.x*256 + threadIdx.x;
  if (idx < NB*AA) out[idx] = g_v[idx >> 3];
}

// ============ Fused half-tile: RNG + layer-1 + HMMA GEMM2 + partial shapley ============
// CTA = (b, half): 64 rows (8 samples x 8 prefixes). 256 threads. 2 CTAs/SM.
// smem layout (bytes)
#define S_AH  0                 // 32768: A hi frags [mblk(4)*16+kblk][lane][reg]
#define S_AL  32768             // 32768: A lo frags
#define S_BH  65536             // 16384: B hi dbuf [buf][2048]
#define S_BL  81920             // 16384: B lo dbuf
#define S_RQ  98304             // 4096:  q transposed [(sgrp*8+j)*16+na][p(2)]
#define S_B2  102400            // 1024
#define S_W3  103424            // 1024
#define S_RED 104448            // 2304: sred[64][9]
#define S_ADV 106752            // 256:  advs[64]
#define S_POS 107008            // 64
#define S_INV 107072            // 256:  s_inv[8][8]
#define SM_TOT 107328

__global__ void __launch_bounds__(256,2) kfused(const float* __restrict__ qs,
                  const float* __restrict__ W1,
                  const float* __restrict__ b2, const float* __restrict__ W3,
                  const float* __restrict__ b3, float* __restrict__ out){
  extern __shared__ __align__(16) char sm[];
  uint32_t* sAh = (uint32_t*)(sm + S_AH);
  uint32_t* sAl = (uint32_t*)(sm + S_AL);
  uint32_t* sBh = (uint32_t*)(sm + S_BH);
  uint32_t* sBl = (uint32_t*)(sm + S_BL);
  float* rqT = (float*)(sm + S_RQ);
  float* b2s = (float*)(sm + S_B2);
  float* w3s = (float*)(sm + S_W3);
  float (*sred)[9] = (float(*)[9])(sm + S_RED);
  float* advs = (float*)(sm + S_ADV);
  unsigned char* poss = (unsigned char*)(sm + S_POS);
  int (*s_inv)[AA] = (int(*)[AA])(sm + S_INV);

  const int tid  = threadIdx.x;
  const int bid  = blockIdx.x;
  const int b    = bid >> 1;
  const int half = bid & 1;

  // stage B chunk 0 + b2/W3
  {
    const uint4* srch = (const uint4*)g_Bh;
    const uint4* srcl = (const uint4*)g_Bl;
    uint4* dsth = (uint4*)sBh;
    uint4* dstl = (uint4*)sBl;
    dsth[tid*2]   = srch[tid*2];
    dsth[tid*2+1] = srch[tid*2+1];
    dstl[tid*2]   = srcl[tid*2];
    dstl[tid*2+1] = srcl[tid*2+1];
  }
  b2s[tid] = b2[tid];
  w3s[tid] = W3[tid];

  // RNG + permutations for this half's 8 samples
  if (tid < 8){
    int sl = tid;                       // local sample
    int s  = half*8 + sl;               // global sample
    unsigned base = (unsigned)((b*SS + s)*AA);
    float u[AA];
    #pragma unroll
    for(int a=0;a<AA;a++){
      uint32_t o0, o1;
      threefry2x32(0u, base + a, o0, o1);
      u[a] = bits_to_unit(o0 ^ o1);
    }
    int ord[AA];
    #pragma unroll
    for(int i=0;i<AA;i++) ord[i]=i;
    for(int i=1;i<AA;i++){
      int oi = ord[i]; float ku = u[oi]; int j=i;
      while(j>0 && u[ord[j-1]] > ku){ ord[j]=ord[j-1]; j--; }
      ord[j]=oi;
    }
    #pragma unroll
    for(int r=0;r<AA;r++) s_inv[sl][ord[r]] = r;
    #pragma unroll
    for(int i=0;i<AA;i++) poss[sl*8 + i] = (unsigned char)ord[i];
  }
  __syncthreads();
  // stage q transposed: rqT[((sgrp*8+j)*16+na)*2 + p] = qs[b, inv[sgrp*2+p][j], na]
  for(int e=tid; e<1024; e+=256){
    int p  = e & 1;
    int na = (e >> 1) & 15;
    int j  = (e >> 5) & 7;
    int sg = e >> 8;            // 0..3
    int sl = sg*2 + p;
    rqT[e] = qs[b*(AA*NACT) + s_inv[sl][j]*NACT + na];
  }
  __syncthreads();

  // ---- layer-1: sgrp(4) x cg(64); W1x via direct LDG; no inner barriers ----
  {
    const int sgrp = tid >> 6;       // 0..3 -> rows sgrp*16 + p*8 + j
    const int cg   = tid & 63;
    const int kblk = cg >> 2;
    const int kp   = cg & 3;
    const int c0   = kblk*16 + kp*2;

    ull acc[2][2];
    {
      ull a01 = *(const ull*)&g_sW1[b*EM + c0];
      ull a89 = *(const ull*)&g_sW1[b*EM + c0 + 8];
      acc[0][0]=a01; acc[0][1]=a89;
      acc[1][0]=a01; acc[1][1]=a89;
    }

    for(int j=0;j<AA;j++){
      #pragma unroll
      for(int na=0;na<NACT;na++){
        const float* wr = &W1[(SD + j*NACT + na)*EM + c0];
        ull w01 = *(const ull*)wr;
        ull w89 = *(const ull*)(wr + 8);
        float2 q2 = *(const float2*)&rqT[((sgrp*8 + j)*16 + na)*2];
        ull q;
        q = pack2(q2.x); fma2(acc[0][0],q,w01); fma2(acc[0][1],q,w89);
        q = pack2(q2.y); fma2(acc[1][0],q,w01); fma2(acc[1][1],q,w89);
      }
      // emit fragment: mblk = sgrp; rows sgrp*16+j and +8
      const int lane = j*4 + kp;
      float2 x0 = unpack2(acc[0][0]);
      float2 x8 = unpack2(acc[0][1]);
      float2 y0 = unpack2(acc[1][0]);
      float2 y8 = unpack2(acc[1][1]);
      uint4 hv, lv;
      split2(fmaxf(x0.x,0.f), fmaxf(x0.y,0.f), hv.x, lv.x);
      split2(fmaxf(y0.x,0.f), fmaxf(y0.y,0.f), hv.y, lv.y);
      split2(fmaxf(x8.x,0.f), fmaxf(x8.y,0.f), hv.z, lv.z);
      split2(fmaxf(y8.x,0.f), fmaxf(y8.y,0.f), hv.w, lv.w);
      int aidx = ((sgrp*16 + kblk)*32 + lane)*4;
      *(uint4*)&sAh[aidx] = hv;
      *(uint4*)&sAl[aidx] = lv;
    }
  }
  __syncthreads();

  // ---- GEMM mainloop: 8 warps = 4 mblk x 2 nh ----
  const int lane = tid & 31;
  const int warp = tid >> 5;
  const int mblk = warp & 3;
  const int nh   = warp >> 2;

  float d[16][4];
  #pragma unroll
  for(int i=0;i<16;i++){ d[i][0]=0.f; d[i][1]=0.f; d[i][2]=0.f; d[i][3]=0.f; }

  for(int kb=0; kb<16; kb++){
    uint4 ph0, ph1, pl0, pl1;
    if (kb < 15){
      const uint4* srch = (const uint4*)(g_Bh + (kb+1)*2048);
      const uint4* srcl = (const uint4*)(g_Bl + (kb+1)*2048);
      ph0 = srch[tid*2]; ph1 = srch[tid*2+1];
      pl0 = srcl[tid*2]; pl1 = srcl[tid*2+1];
    }
    uint32_t ah[4], al[4];
    {
      int aidx = ((mblk*16 + kb)*32 + lane)*4;
      *(uint4*)ah = *(const uint4*)&sAh[aidx];
      *(uint4*)al = *(const uint4*)&sAl[aidx];
    }
    const uint32_t* curh = &sBh[(kb&1)*2048];
    const uint32_t* curl = &sBl[(kb&1)*2048];
    #pragma unroll
    for(int nb=0; nb<16; nb++){
      int ng  = nh*16 + nb;
      int off = (ng*32 + lane)*2;
      uint2 bh = *(const uint2*)&curh[off];
      uint2 bl = *(const uint2*)&curl[off];
      mma16816(d[nb], ah, bh.x, bh.y);
      mma16816(d[nb], al, bh.x, bh.y);
      mma16816(d[nb], ah, bl.x, bl.y);
    }
    if (kb < 15){
      uint4* dsth = (uint4*)&sBh[((kb+1)&1)*2048];
      uint4* dstl = (uint4*)&sBl[((kb+1)&1)*2048];
      dsth[tid*2] = ph0; dsth[tid*2+1] = ph1;
      dstl[tid*2] = pl0; dstl[tid*2+1] = pl1;
    }
    __syncthreads();
  }

  // ---- epilogue: relu(d + b2) dot W3, quad shfl-reduce ----
  float p0 = 0.f, p1 = 0.f;
  #pragma unroll
  for(int nb=0; nb<16; nb++){
    int c0 = (nh*16 + nb)*8 + (lane&3)*2;
    float w0 = w3s[c0], w1 = w3s[c0+1];
    float bb0 = b2s[c0], bb1 = b2s[c0+1];
    p0 += fmaxf(d[nb][0]+bb0, 0.f)*w0 + fmaxf(d[nb][1]+bb1, 0.f)*w1;
    p1 += fmaxf(d[nb][2]+bb0, 0.f)*w0 + fmaxf(d[nb][3]+bb1, 0.f)*w1;
  }
  p0 += __shfl_xor_sync(0xFFFFFFFFu, p0, 1);
  p0 += __shfl_xor_sync(0xFFFFFFFFu, p0, 2);
  p1 += __shfl_xor_sync(0xFFFFFFFFu, p1, 1);
  p1 += __shfl_xor_sync(0xFFFFFFFFu, p1, 2);
  if ((lane & 3) == 0){
    int r0 = mblk*16 + (lane>>2);
    sred[r0  ][nh] = p0;
    sred[r0+8][nh] = p1;
  }
  __syncthreads();
  if (tid < 64){
    advs[tid] = b3[0] + sred[tid][0] + sred[tid][1];
  }
  __syncthreads();
  // partial shapley over this half's 8 samples
  if (tid < 8){
    float sum = 0.f;
    #pragma unroll
    for(int sl=0;sl<8;sl++){
      sum += advs[sl*8 + (int)poss[sl*8 + tid]];
    }
    atomicAdd(&out[b*8 + tid], sum * (1.0f/16.0f));
  }
}

extern "C" void kernel_launch(void* const* d_in, const int* in_sizes, int n_in,
                              void* d_out, int out_size){
  const float* states   = (const float*)d_in[0];
  const float* agent_qs = (const float*)d_in[1];
  const float* W1  = (const float*)d_in[2];
  const float* b1  = (const float*)d_in[3];
  const float* W2  = (const float*)d_in[4];
  const float* b2  = (const float*)d_in[5];
  const float* W3  = (const float*)d_in[6];
  const float* b3  = (const float*)d_in[7];
  const float* Vw1 = (const float*)d_in[8];
  const float* Vb1 = (const float*)d_in[9];
  const float* Vw2 = (const float*)d_in[10];
  const float* Vb2 = (const float*)d_in[11];
  float* out = (float*)d_out;

  cudaFuncSetAttribute(kfused, cudaFuncAttributeMaxDynamicSharedMemorySize, SM_TOT);

  k0_prepW2<<<128, 256>>>(W2);
  k1_state <<<NB/4, 256>>>(states, W1, b1, Vw1, Vb1, Vw2, Vb2);
  kinit_out<<<(NB*AA + 255)/256, 256>>>(out);
  kfused   <<<NB*2, 256, SM_TOT>>>(agent_qs, W1, b2, W3, b3, out);
}

// round 13
// speedup vs baseline: 1.6764x; 1.0150x over previous
#include <cuda_runtime.h>
#include <cuda_bf16.h>
#include <stdint.h>

typedef unsigned long long ull;

#define NB   1024
#define SS   16
#define AA   8
#define NACT 16
#define SD   256
#define EM   256

// ---------------- device scratch ----------------
__device__ float g_sW1[NB*EM];
__device__ float g_v[NB];
// W2 B-fragments: [kblk(16)][nblk(32)][lane(32)][reg(2)] u32 (split hi/lo)
__device__ uint32_t g_Bh[16*32*32*2];
__device__ uint32_t g_Bl[16*32*32*2];

// ---------------- threefry2x32 (JAX exact, key(42)) ----------------
__device__ __forceinline__ uint32_t rotl(uint32_t x, int r){ return (x<<r)|(x>>(32-r)); }
__device__ __forceinline__ void threefry2x32(uint32_t c0, uint32_t c1, uint32_t &o0, uint32_t &o1){
  const uint32_t k0 = 0u, k1v = 42u, k2 = 0u ^ 42u ^ 0x1BD11BDAu;
  uint32_t x0 = c0 + k0;
  uint32_t x1 = c1 + k1v;
#define TF_R(rot) { x0 += x1; x1 = rotl(x1, rot); x1 ^= x0; }
  TF_R(13) TF_R(15) TF_R(26) TF_R(6)
  x0 += k1v; x1 += k2 + 1u;
  TF_R(17) TF_R(29) TF_R(16) TF_R(24)
  x0 += k2;  x1 += k0 + 2u;
  TF_R(13) TF_R(15) TF_R(26) TF_R(6)
  x0 += k0;  x1 += k1v + 3u;
  TF_R(17) TF_R(29) TF_R(16) TF_R(24)
  x0 += k1v; x1 += k2 + 4u;
  TF_R(13) TF_R(15) TF_R(26) TF_R(6)
  x0 += k2;  x1 += k0 + 5u;
#undef TF_R
  o0 = x0; o1 = x1;
}
__device__ __forceinline__ float bits_to_unit(uint32_t bits){
  return __uint_as_float(0x3f800000u | (bits >> 9)) - 1.0f;
}

// ---------------- packed helpers ----------------
__device__ __forceinline__ ull pack2(float x){
  ull r; unsigned u = __float_as_uint(x);
  asm("mov.b64 %0, {%1,%1};" : "=l"(r) : "r"(u));
  return r;
}
__device__ __forceinline__ void fma2(ull& d, ull a, ull b){
  asm("fma.rn.f32x2 %0, %1, %2, %0;" : "+l"(d) : "l"(a), "l"(b));
}
__device__ __forceinline__ float2 unpack2(ull v){
  unsigned lo, hi; asm("mov.b64 {%0,%1}, %2;" : "=r"(lo), "=r"(hi) : "l"(v));
  return make_float2(__uint_as_float(lo), __uint_as_float(hi));
}
__device__ __forceinline__ uint32_t pack_bf16x2(float v0, float v1){
  uint32_t r;
  asm("cvt.rn.bf16x2.f32 %0, %1, %2;" : "=r"(r) : "f"(v1), "f"(v0));
  return r;
}
__device__ __forceinline__ void split2(float v0, float v1, uint32_t &h, uint32_t &l){
  h = pack_bf16x2(v0, v1);
  float h0 = __uint_as_float(h << 16);
  float h1 = __uint_as_float(h & 0xFFFF0000u);
  l = pack_bf16x2(v0 - h0, v1 - h1);
}
__device__ __forceinline__ void split_bf16(float v, uint32_t &h, uint32_t &l){
  __nv_bfloat16 hb = __float2bfloat16(v);
  float lf = v - __bfloat162float(hb);
  __nv_bfloat16 lb = __float2bfloat16(lf);
  h = (uint32_t)__bfloat16_as_ushort(hb);
  l = (uint32_t)__bfloat16_as_ushort(lb);
}

__device__ __forceinline__ void mma16816(float* d, const uint32_t* a, uint32_t b0, uint32_t b1){
  asm volatile("mma.sync.aligned.m16n8k16.row.col.f32.bf16.bf16.f32 "
    "{%0,%1,%2,%3}, {%4,%5,%6,%7}, {%8,%9}, {%0,%1,%2,%3};"
    : "+f"(d[0]),"+f"(d[1]),"+f"(d[2]),"+f"(d[3])
    : "r"(a[0]),"r"(a[1]),"r"(a[2]),"r"(a[3]), "r"(b0),"r"(b1));
}

// ============ K0: W2 -> B fragments ============
__global__ void k0_prepW2(const float* __restrict__ W2){
  int idx = blockIdx.x*256 + threadIdx.x;   // 32768
  int kp = idx >> 8, n = idx & 255;
  int k = kp*2;
  float v0 = W2[k*EM + n];
  float v1 = W2[(k+1)*EM + n];
  uint32_t h0,l0,h1,l1;
  split_bf16(v0,h0,l0); split_bf16(v1,h1,l1);
  uint32_t hi = h0 | (h1<<16);
  uint32_t lo = l0 | (l1<<16);
  int kblk = kp>>3;
  int reg  = (kp>>2)&1;
  int lane = (n&7)*4 + (kp&3);
  int nblk = n>>3;
  int bidx = ((kblk*32+nblk)*32+lane)*2 + reg;
  g_Bh[bidx] = hi;
  g_Bl[bidx] = lo;
}

// ============ K1: per-b state terms, 4 b per CTA ============
__global__ void __launch_bounds__(256) k1_state(const float* __restrict__ st,
                         const float* __restrict__ W1,
                         const float* __restrict__ b1, const float* __restrict__ Vw1,
                         const float* __restrict__ Vb1, const float* __restrict__ Vw2,
                         const float* __restrict__ Vb2){
  const int b0 = blockIdx.x * 4;
  const int n  = threadIdx.x;
  __shared__ float s_st[4][SD];
  __shared__ float red[4][EM];
  #pragma unroll
  for(int bi=0;bi<4;bi++) s_st[bi][n] = st[(b0+bi)*SD + n];
  __syncthreads();
  float acc[4], accv[4];
  float bb1 = b1[n], vbb = Vb1[n];
  #pragma unroll
  for(int bi=0;bi<4;bi++){ acc[bi]=bb1; accv[bi]=vbb; }
  #pragma unroll 4
  for(int k=0;k<SD;k++){
    float w  = W1 [k*EM + n];
    float vw = Vw1[k*EM + n];
    #pragma unroll
    for(int bi=0;bi<4;bi++){
      float sv = s_st[bi][k];
      acc[bi]  = fmaf(sv, w,  acc[bi]);
      accv[bi] = fmaf(sv, vw, accv[bi]);
    }
  }
  float vw2 = Vw2[n];
  #pragma unroll
  for(int bi=0;bi<4;bi++){
    g_sW1[(b0+bi)*EM + n] = acc[bi];
    red[bi][n] = fmaxf(accv[bi], 0.f) * vw2;
  }
  __syncthreads();
  int w = n >> 5, l = n & 31;
  if (w < 4){
    float s = 0.f;
    #pragma unroll
    for(int t=0;t<8;t++) s += red[w][l + t*32];
    #pragma unroll
    for(int off=16; off>0; off>>=1) s += __shfl_xor_sync(0xFFFFFFFFu, s, off);
    if (l == 0) g_v[b0 + w] = s + Vb2[0];
  }
}

// ============ Fused 128-row: RNG + layer-1 (direct LDG) + HMMA 2mblk x 8nb + shapley ============
// smem layout (bytes)
#define S_AH  0                 // 65536: A hi frags [mblk(8)*16+kblk][lane][reg]
#define S_AL  65536             // 65536: A lo frags
#define S_BH  131072            // 16384: B hi dbuf [buf][2048]
#define S_BL  147456            // 16384: B lo dbuf
#define S_RQ  163840            // 8192:  q transposed [(sgrp*8+j)*16+na][p(2)]
#define S_B2  172032            // 1024
#define S_W3  173056            // 1024
#define S_RED 174080            // 2560: sred[128][5]
#define S_ADV 176640            // 512:  advs[128]
#define S_POS 177152            // 128
#define S_INV 177280            // 512:  s_inv[16][8]
#define SM_TOT 177792

__global__ void __launch_bounds__(512,1) kfused(const float* __restrict__ qs,
                  const float* __restrict__ W1,
                  const float* __restrict__ b2, const float* __restrict__ W3,
                  const float* __restrict__ b3, float* __restrict__ out){
  extern __shared__ __align__(16) char sm[];
  uint32_t* sAh = (uint32_t*)(sm + S_AH);
  uint32_t* sAl = (uint32_t*)(sm + S_AL);
  uint32_t* sBh = (uint32_t*)(sm + S_BH);
  uint32_t* sBl = (uint32_t*)(sm + S_BL);
  float* rqT = (float*)(sm + S_RQ);
  float* b2s = (float*)(sm + S_B2);
  float* w3s = (float*)(sm + S_W3);
  float (*sred)[5] = (float(*)[5])(sm + S_RED);
  float* advs = (float*)(sm + S_ADV);
  unsigned char* poss = (unsigned char*)(sm + S_POS);
  int (*s_inv)[AA] = (int(*)[AA])(sm + S_INV);

  const int tid = threadIdx.x;
  const int b   = blockIdx.x;

  // stage B chunk 0 + b2/W3
  {
    const uint4* srch = (const uint4*)g_Bh;
    const uint4* srcl = (const uint4*)g_Bl;
    ((uint4*)sBh)[tid] = srch[tid];
    ((uint4*)sBl)[tid] = srcl[tid];
  }
  if (tid < 256){ b2s[tid] = b2[tid]; w3s[tid] = W3[tid]; }

  // RNG + permutations (16 samples)
  if (tid < SS){
    int s = tid;
    unsigned base = (unsigned)((b*SS + s)*AA);
    float u[AA];
    #pragma unroll
    for(int a=0;a<AA;a++){
      uint32_t o0, o1;
      threefry2x32(0u, base + a, o0, o1);
      u[a] = bits_to_unit(o0 ^ o1);
    }
    int ord[AA];
    #pragma unroll
    for(int i=0;i<AA;i++) ord[i]=i;
    for(int i=1;i<AA;i++){
      int oi = ord[i]; float ku = u[oi]; int j=i;
      while(j>0 && u[ord[j-1]] > ku){ ord[j]=ord[j-1]; j--; }
      ord[j]=oi;
    }
    #pragma unroll
    for(int r=0;r<AA;r++) s_inv[s][ord[r]] = r;
    #pragma unroll
    for(int i=0;i<AA;i++) poss[s*8 + i] = (unsigned char)ord[i];
  }
  __syncthreads();
  // stage q transposed: rqT[((sgrp*8+j)*16+na)*2 + p] = qs[b, inv[sgrp*2+p][j], na]
  for(int e=tid; e<2048; e+=512){
    int p  = e & 1;
    int na = (e >> 1) & 15;
    int j  = (e >> 5) & 7;
    int sg = e >> 8;            // 0..7
    int s  = sg*2 + p;
    rqT[e] = qs[b*(AA*NACT) + s_inv[s][j]*NACT + na];
  }
  __syncthreads();

  // ---- layer-1: sgrp(8) x cg(64); W1x via direct LDG; no inner barriers ----
  {
    const int sgrp = tid >> 6;       // 0..7 -> mblk
    const int cg   = tid & 63;
    const int kblk = cg >> 2;
    const int kp   = cg & 3;
    const int c0   = kblk*16 + kp*2;

    ull acc[2][2];
    {
      ull a01 = *(const ull*)&g_sW1[b*EM + c0];
      ull a89 = *(const ull*)&g_sW1[b*EM + c0 + 8];
      acc[0][0]=a01; acc[0][1]=a89;
      acc[1][0]=a01; acc[1][1]=a89;
    }

    for(int j=0;j<AA;j++){
      #pragma unroll
      for(int na=0;na<NACT;na++){
        const float* wr = &W1[(SD + j*NACT + na)*EM + c0];
        ull w01 = *(const ull*)wr;
        ull w89 = *(const ull*)(wr + 8);
        float2 q2 = *(const float2*)&rqT[((sgrp*8 + j)*16 + na)*2];
        ull q;
        q = pack2(q2.x); fma2(acc[0][0],q,w01); fma2(acc[0][1],q,w89);
        q = pack2(q2.y); fma2(acc[1][0],q,w01); fma2(acc[1][1],q,w89);
      }
      // emit fragment: mblk = sgrp; fragment rows j (p=0) and j+8 (p=1)
      const int lane = j*4 + kp;
      float2 x0 = unpack2(acc[0][0]);
      float2 x8 = unpack2(acc[0][1]);
      float2 y0 = unpack2(acc[1][0]);
      float2 y8 = unpack2(acc[1][1]);
      uint4 hv, lv;
      split2(fmaxf(x0.x,0.f), fmaxf(x0.y,0.f), hv.x, lv.x);
      split2(fmaxf(y0.x,0.f), fmaxf(y0.y,0.f), hv.y, lv.y);
      split2(fmaxf(x8.x,0.f), fmaxf(x8.y,0.f), hv.z, lv.z);
      split2(fmaxf(y8.x,0.f), fmaxf(y8.y,0.f), hv.w, lv.w);
      int aidx = ((sgrp*16 + kblk)*32 + lane)*4;
      *(uint4*)&sAh[aidx] = hv;
      *(uint4*)&sAl[aidx] = lv;
    }
  }
  __syncthreads();

  // ---- GEMM mainloop: 16 warps = 4 mpair x 4 ngrp; 2 mblk x 8 nb per warp ----
  const int lane  = tid & 31;
  const int warp  = tid >> 5;
  const int mpair = warp >> 2;     // 0..3
  const int ngrp  = warp & 3;      // 0..3

  float d[2][8][4];
  #pragma unroll
  for(int i=0;i<2;i++)
    #pragma unroll
    for(int nb=0;nb<8;nb++){ d[i][nb][0]=0.f; d[i][nb][1]=0.f; d[i][nb][2]=0.f; d[i][nb][3]=0.f; }

  for(int kb=0; kb<16; kb++){
    uint4 ph, pl;
    if (kb < 15){
      ph = ((const uint4*)(g_Bh + (kb+1)*2048))[tid];
      pl = ((const uint4*)(g_Bl + (kb+1)*2048))[tid];
    }
    uint32_t ah[2][4], al[2][4];
    #pragma unroll
    for(int i=0;i<2;i++){
      int aidx = (((mpair*2+i)*16 + kb)*32 + lane)*4;
      *(uint4*)ah[i] = *(const uint4*)&sAh[aidx];
      *(uint4*)al[i] = *(const uint4*)&sAl[aidx];
    }
    const uint32_t* curh = &sBh[(kb&1)*2048];
    const uint32_t* curl = &sBl[(kb&1)*2048];
    #pragma unroll
    for(int nb=0; nb<8; nb++){
      int ng  = ngrp*8 + nb;
      int off = (ng*32 + lane)*2;
      uint2 bh = *(const uint2*)&curh[off];
      uint2 bl = *(const uint2*)&curl[off];
      #pragma unroll
      for(int i=0;i<2;i++){
        mma16816(d[i][nb], ah[i], bh.x, bh.y);
        mma16816(d[i][nb], al[i], bh.x, bh.y);
        mma16816(d[i][nb], ah[i], bl.x, bl.y);
      }
    }
    if (kb < 15){
      ((uint4*)&sBh[((kb+1)&1)*2048])[tid] = ph;
      ((uint4*)&sBl[((kb+1)&1)*2048])[tid] = pl;
    }
    __syncthreads();
  }

  // ---- epilogue: relu(d + b2) dot W3, quad shfl-reduce ----
  float p[2][2];
  p[0][0]=0.f; p[0][1]=0.f; p[1][0]=0.f; p[1][1]=0.f;
  #pragma unroll
  for(int nb=0; nb<8; nb++){
    int c0 = (ngrp*8 + nb)*8 + (lane&3)*2;
    float w0 = w3s[c0], w1 = w3s[c0+1];
    float bb0 = b2s[c0], bb1 = b2s[c0+1];
    #pragma unroll
    for(int i=0;i<2;i++){
      p[i][0] += fmaxf(d[i][nb][0]+bb0,0.f)*w0 + fmaxf(d[i][nb][1]+bb1,0.f)*w1;
      p[i][1] += fmaxf(d[i][nb][2]+bb0,0.f)*w0 + fmaxf(d[i][nb][3]+bb1,0.f)*w1;
    }
  }
  #pragma unroll
  for(int i=0;i<2;i++){
    #pragma unroll
    for(int h=0;h<2;h++){
      p[i][h] += __shfl_xor_sync(0xFFFFFFFFu, p[i][h], 1);
      p[i][h] += __shfl_xor_sync(0xFFFFFFFFu, p[i][h], 2);
    }
  }
  if ((lane & 3) == 0){
    #pragma unroll
    for(int i=0;i<2;i++){
      int r0 = (mpair*2+i)*16 + (lane>>2);
      sred[r0  ][ngrp] = p[i][0];
      sred[r0+8][ngrp] = p[i][1];
    }
  }
  __syncthreads();
  if (tid < 128){
    advs[tid] = b3[0] + sred[tid][0] + sred[tid][1] + sred[tid][2] + sred[tid][3];
  }
  __syncthreads();
  if (tid < 8){
    float sum = 0.f;
    #pragma unroll
    for(int s=0;s<SS;s++){
      sum += advs[s*8 + (int)poss[s*8 + tid]];
    }
    out[b*8 + tid] = g_v[b] + sum * (1.0f/16.0f);
  }
}

extern "C" void kernel_launch(void* const* d_in, const int* in_sizes, int n_in,
                              void* d_out, int out_size){
  const float* states   = (const float*)d_in[0];
  const float* agent_qs = (const float*)d_in[1];
  const float* W1  = (const float*)d_in[2];
  const float* b1  = (const float*)d_in[3];
  const float* W2  = (const float*)d_in[4];
  const float* b2  = (const float*)d_in[5];
  const float* W3  = (const float*)d_in[6];
  const float* b3  = (const float*)d_in[7];
  const float* Vw1 = (const float*)d_in[8];
  const float* Vb1 = (const float*)d_in[9];
  const float* Vw2 = (const float*)d_in[10];
  const float* Vb2 = (const float*)d_in[11];
  float* out = (float*)d_out;

  cudaFuncSetAttribute(kfused, cudaFuncAttributeMaxDynamicSharedMemorySize, SM_TOT);

  k0_prepW2<<<128, 256>>>(W2);
  k1_state <<<NB/4, 256>>>(states, W1, b1, Vw1, Vb1, Vw2, Vb2);
  kfused   <<<NB, 512, SM_TOT>>>(agent_qs, W1, b2, W3, b3, out);
}